// round 8
// baseline (speedup 1.0000x reference)
#include <cuda_runtime.h>
#include <cuda_bf16.h>
#include <cstdint>

#define H 256
#define NMAX 100000
#define NPAD 100096
#define EMAX 320000

// ---------------- scratch (__device__ globals; no allocation allowed) --------
__device__ unsigned short g_ah[3][NPAD * H];    // agg rows, bf16 hi (row-major [m][k])
__device__ unsigned short g_al[3][NPAD * H];    // agg rows, bf16 lo
__device__ unsigned short g_wh[3][H * H];       // W^T hi (bf16 bits), [n][k]
__device__ unsigned short g_wl[3][H * H];       // W^T lo (bf16 bits)
__device__ int            g_deg[NMAX];
__device__ int            g_off[NMAX];
__device__ int            g_cur[NMAX];
__device__ int            g_eid[EMAX];
__device__ int            g_bsum[128];

// ---------------- helpers ----------------------------------------------------
__device__ __forceinline__ uint32_t smem_u32(const void* p) {
    uint32_t a;
    asm("{ .reg .u64 t; cvta.to.shared.u64 t, %1; cvt.u32.u64 %0, t; }"
        : "=r"(a) : "l"(p));
    return a;
}
__device__ __forceinline__ void ldsm_x4(uint32_t r[4], uint32_t addr) {
    asm volatile("ldmatrix.sync.aligned.m8n8.x4.shared.b16 {%0,%1,%2,%3}, [%4];"
                 : "=r"(r[0]), "=r"(r[1]), "=r"(r[2]), "=r"(r[3]) : "r"(addr));
}
__device__ __forceinline__ void mma_bf16(float d[4], const uint32_t a[4],
                                         const uint32_t b[2]) {
    asm volatile(
        "mma.sync.aligned.m16n8k16.row.col.f32.bf16.bf16.f32 "
        "{%0,%1,%2,%3}, {%4,%5,%6,%7}, {%8,%9}, {%0,%1,%2,%3};"
        : "+f"(d[0]), "+f"(d[1]), "+f"(d[2]), "+f"(d[3])
        : "r"(a[0]), "r"(a[1]), "r"(a[2]), "r"(a[3]), "r"(b[0]), "r"(b[1]));
}
__device__ __forceinline__ void cp16(uint32_t dst, const void* src) {
    asm volatile("cp.async.cg.shared.global [%0], [%1], 16;"
                 :: "r"(dst), "l"(src) : "memory");
}
#define CP_COMMIT asm volatile("cp.async.commit_group;" ::: "memory")
#define CP_WAIT0  asm volatile("cp.async.wait_group 0;" ::: "memory")
#define CP_WAIT1  asm volatile("cp.async.wait_group 1;" ::: "memory")

__device__ __forceinline__ float wsum(float v) {
#pragma unroll
    for (int o = 16; o; o >>= 1) v += __shfl_xor_sync(0xffffffffu, v, o);
    return v;
}
__device__ __forceinline__ unsigned short bf_hi(float x, float& res) {
    __nv_bfloat16 h = __float2bfloat16(x);
    res = x - __bfloat162float(h);
    return __bfloat16_as_ushort(h);
}
// split 4 floats -> hi uint2 + lo uint2, streaming store
__device__ __forceinline__ void split_store4(unsigned short* ph, unsigned short* pl,
                                             float4 v) {
    float r0, r1, r2, r3;
    unsigned short h0 = bf_hi(v.x, r0), h1 = bf_hi(v.y, r1);
    unsigned short h2 = bf_hi(v.z, r2), h3 = bf_hi(v.w, r3);
    uint2 hh, ll;
    hh.x = ((uint32_t)h1 << 16) | h0;
    hh.y = ((uint32_t)h3 << 16) | h2;
    ll.x = ((uint32_t)__bfloat16_as_ushort(__float2bfloat16(r1)) << 16) |
           __bfloat16_as_ushort(__float2bfloat16(r0));
    ll.y = ((uint32_t)__bfloat16_as_ushort(__float2bfloat16(r3)) << 16) |
           __bfloat16_as_ushort(__float2bfloat16(r2));
    __stcs(reinterpret_cast<uint2*>(ph), hh);
    __stcs(reinterpret_cast<uint2*>(pl), ll);
}

// ------------------------------------------------- W -> W^T bf16 hi/lo split
__global__ void k_wconv(const float* __restrict__ w0, const float* __restrict__ w1,
                        const float* __restrict__ w2) {
    int i = blockIdx.x * blockDim.x + threadIdx.x;
    if (i >= 3 * H * H) return;
    int g = i >> 16;
    int r = i & 0xFFFF;
    int k = r >> 8, n = r & 255;
    const float* w = (g == 0) ? w0 : (g == 1) ? w1 : w2;
    float v = w[k * H + n];
    float lo;
    unsigned short hi = bf_hi(v, lo);
    g_wh[g][n * H + k] = hi;
    g_wl[g][n * H + k] = __bfloat16_as_ushort(__float2bfloat16(lo));
}

// ---------------------------------------------------------------- CSR build
__global__ void k_zero(int N) {
    int i = blockIdx.x * blockDim.x + threadIdx.x;
    if (i < N) { g_deg[i] = 0; g_cur[i] = 0; }
}
__global__ void k_hist(const int* __restrict__ dst, int E) {
    int e = blockIdx.x * blockDim.x + threadIdx.x;
    if (e < E) atomicAdd(&g_deg[dst[e]], 1);
}
__global__ void k_scan_block(int N) {
    __shared__ int sm[1024];
    int tid = threadIdx.x;
    int i = blockIdx.x * 1024 + tid;
    int v = (i < N) ? g_deg[i] : 0;
    sm[tid] = v;
    __syncthreads();
#pragma unroll
    for (int o = 1; o < 1024; o <<= 1) {
        int t = (tid >= o) ? sm[tid - o] : 0;
        __syncthreads();
        sm[tid] += t;
        __syncthreads();
    }
    if (i < N) g_off[i] = sm[tid] - v;  // exclusive
    if (tid == 1023) g_bsum[blockIdx.x] = sm[1023];
}
__global__ void k_scan_top(int nb) {
    if (threadIdx.x == 0 && blockIdx.x == 0) {
        int run = 0;
        for (int b = 0; b < nb; b++) { int t = g_bsum[b]; g_bsum[b] = run; run += t; }
    }
}
__global__ void k_scan_add(int N) {
    int i = blockIdx.x * blockDim.x + threadIdx.x;
    if (i < N) g_off[i] += g_bsum[i >> 10];
}
__global__ void k_permute(const int* __restrict__ dst, int E) {
    int e = blockIdx.x * blockDim.x + threadIdx.x;
    if (e >= E) return;
    int d = dst[e];
    int slot = g_off[d] + atomicAdd(&g_cur[d], 1);
    g_eid[slot] = e;
}

// ------------------------------------------ fused edge pass: warp per dst node
// Online softmax over incoming edges for 3 heads; register accumulation; writes
// pre-split bf16 hi/lo agg rows once (streaming stores).
__global__ __launch_bounds__(256) void k_edge(
    const float* __restrict__ ent, const float* __restrict__ rel,
    const int* __restrict__ src, const int* __restrict__ rid,
    const int* __restrict__ nid, int N) {
    int w = (blockIdx.x * 256 + threadIdx.x) >> 5;
    if (w >= N) return;
    const int lane = threadIdx.x & 31;
    const int d = w;
    const int dn = nid[d];
    const float4* ent4 = reinterpret_cast<const float4*>(ent);
    const float4* rel4 = reinterpret_cast<const float4*>(rel);
    const float4 hda = ent4[(size_t)dn * 64 + lane];
    const float4 hdb = ent4[(size_t)dn * 64 + lane + 32];

    const int off0 = g_off[d];
    const int deg = g_deg[d];

    float m0 = -1e30f, m1 = -1e30f, m2 = -1e30f;
    float s0 = 0.f, s1 = 0.f, s2 = 0.f;
    float4 a0a = {0, 0, 0, 0}, a0b = {0, 0, 0, 0};
    float4 a1a = {0, 0, 0, 0}, a1b = {0, 0, 0, 0};
    float4 a2a = {0, 0, 0, 0}, a2b = {0, 0, 0, 0};

    for (int j = 0; j < deg; j++) {
        int eid = g_eid[off0 + j];
        int sn = nid[src[eid]];
        int rr = rid[eid];
        float4 sa = ent4[(size_t)sn * 64 + lane];
        float4 sb = ent4[(size_t)sn * 64 + lane + 32];
        float4 ea = rel4[(size_t)rr * 64 + lane];
        float4 eb = rel4[(size_t)rr * 64 + lane + 32];
        float pe = ea.x * hda.x + ea.y * hda.y + ea.z * hda.z + ea.w * hda.w
                 + eb.x * hdb.x + eb.y * hdb.y + eb.z * hdb.z + eb.w * hdb.w;
        float pn = sa.x * hda.x + sa.y * hda.y + sa.z * hda.z + sa.w * hda.w
                 + sb.x * hdb.x + sb.y * hdb.y + sb.z * hdb.z + sb.w * hdb.w;
        float pc = sa.x * ea.x * hda.x + sa.y * ea.y * hda.y
                 + sa.z * ea.z * hda.z + sa.w * ea.w * hda.w
                 + sb.x * eb.x * hdb.x + sb.y * eb.y * hdb.y
                 + sb.z * eb.z * hdb.z + sb.w * eb.w * hdb.w;
        float de = wsum(pe), dn_ = wsum(pn), dc = wsum(pc);
        float nm0 = fmaxf(m0, de), c0 = expf(m0 - nm0), w0 = expf(de - nm0);
        float nm1 = fmaxf(m1, dn_), c1 = expf(m1 - nm1), w1 = expf(dn_ - nm1);
        float nm2 = fmaxf(m2, dc), c2 = expf(m2 - nm2), w2 = expf(dc - nm2);
        m0 = nm0; m1 = nm1; m2 = nm2;
        s0 = s0 * c0 + w0; s1 = s1 * c1 + w1; s2 = s2 * c2 + w2;
        a0a.x = a0a.x * c0 + ea.x * w0; a0a.y = a0a.y * c0 + ea.y * w0;
        a0a.z = a0a.z * c0 + ea.z * w0; a0a.w = a0a.w * c0 + ea.w * w0;
        a0b.x = a0b.x * c0 + eb.x * w0; a0b.y = a0b.y * c0 + eb.y * w0;
        a0b.z = a0b.z * c0 + eb.z * w0; a0b.w = a0b.w * c0 + eb.w * w0;
        a1a.x = a1a.x * c1 + sa.x * w1; a1a.y = a1a.y * c1 + sa.y * w1;
        a1a.z = a1a.z * c1 + sa.z * w1; a1a.w = a1a.w * c1 + sa.w * w1;
        a1b.x = a1b.x * c1 + sb.x * w1; a1b.y = a1b.y * c1 + sb.y * w1;
        a1b.z = a1b.z * c1 + sb.z * w1; a1b.w = a1b.w * c1 + sb.w * w1;
        a2a.x = a2a.x * c2 + sa.x * ea.x * w2; a2a.y = a2a.y * c2 + sa.y * ea.y * w2;
        a2a.z = a2a.z * c2 + sa.z * ea.z * w2; a2a.w = a2a.w * c2 + sa.w * ea.w * w2;
        a2b.x = a2b.x * c2 + sb.x * eb.x * w2; a2b.y = a2b.y * c2 + sb.y * eb.y * w2;
        a2b.z = a2b.z * c2 + sb.z * eb.z * w2; a2b.w = a2b.w * c2 + sb.w * eb.w * w2;
    }
    float i0 = (s0 > 0.f) ? 1.f / s0 : 0.f;
    float i1 = (s1 > 0.f) ? 1.f / s1 : 0.f;
    float i2 = (s2 > 0.f) ? 1.f / s2 : 0.f;
    size_t base = (size_t)d * H + 4 * lane;
    split_store4(g_ah[0] + base, g_al[0] + base,
                 make_float4(a0a.x * i0, a0a.y * i0, a0a.z * i0, a0a.w * i0));
    split_store4(g_ah[0] + base + 128, g_al[0] + base + 128,
                 make_float4(a0b.x * i0, a0b.y * i0, a0b.z * i0, a0b.w * i0));
    split_store4(g_ah[1] + base, g_al[1] + base,
                 make_float4(a1a.x * i1, a1a.y * i1, a1a.z * i1, a1a.w * i1));
    split_store4(g_ah[1] + base + 128, g_al[1] + base + 128,
                 make_float4(a1b.x * i1, a1b.y * i1, a1b.z * i1, a1b.w * i1));
    split_store4(g_ah[2] + base, g_al[2] + base,
                 make_float4(a2a.x * i2, a2a.y * i2, a2a.z * i2, a2a.w * i2));
    split_store4(g_ah[2] + base + 128, g_al[2] + base + 128,
                 make_float4(a2b.x * i2, a2b.y * i2, a2b.z * i2, a2b.w * i2));
}

// ---------------------------------------------------------------- mma.sync split-bf16 GEMM
// CTA: 128x128 tile; 512 threads = 16 warps (4m x 4n), warp tile 32x32.
// 12 flattened chunks (3 g x 4 k-chunks), 3-stage cp.async pipeline.
#define PCH 72                               // smem pitch (bf16 elems) = 144 B
#define KC 64
#define TILE_BYTES (128 * PCH * 2)           // 18432
#define STAGE_BYTES (4 * TILE_BYTES)         // Ah | Al | Bh | Bl = 73728
#define GEMM_SMEM (3 * STAGE_BYTES)          // 221184

__device__ __forceinline__ void cp_chunk(int cc, uint32_t stg, int m0, int n0) {
    const int g = cc >> 2, c = cc & 3;
    const int k0 = c * KC;
    const int tid = threadIdx.x;
#pragma unroll
    for (int q = 0; q < 2; q++) {
        int idx = q * 512 + tid;
        int row = idx >> 3, oct = idx & 7;
        uint32_t off = (uint32_t)(row * (PCH * 2) + oct * 16);
        size_t gi = (size_t)(m0 + row) * H + k0 + oct * 8;
        cp16(stg + off, g_ah[g] + gi);
        cp16(stg + TILE_BYTES + off, g_al[g] + gi);
    }
#pragma unroll
    for (int q = 0; q < 2; q++) {
        int idx = q * 512 + tid;
        int row = idx >> 3, oct = idx & 7;
        uint32_t off = (uint32_t)(row * (PCH * 2) + oct * 16);
        size_t gi = (size_t)(n0 + row) * H + k0 + oct * 8;
        cp16(stg + 2 * TILE_BYTES + off, g_wh[g] + gi);
        cp16(stg + 3 * TILE_BYTES + off, g_wl[g] + gi);
    }
}

__global__ __launch_bounds__(512, 1)
void k_gemm_mma(const float* __restrict__ ent, float* __restrict__ out, int N) {
    extern __shared__ char smem[];
    const uint32_t sb = smem_u32(smem);
    const int tid = threadIdx.x;
    const int lane = tid & 31, wid = tid >> 5;
    const int wm = wid >> 2, wn = wid & 3;
    const int mbase = wm * 32, nbase = wn * 32;
    const int m0 = blockIdx.y * 128, n0 = blockIdx.x * 128;

    const int a_row = (lane & 7) + ((lane >> 3) & 1) * 8;
    const int a_kof = (lane >> 4) * 8;
    const int b_row = (lane & 7) + (lane >> 4) * 8;
    const int b_kof = ((lane >> 3) & 1) * 8;

    float osum[2][4][4], acc[2][4][4];
#pragma unroll
    for (int f = 0; f < 2; f++)
#pragma unroll
        for (int nf = 0; nf < 4; nf++)
#pragma unroll
            for (int i = 0; i < 4; i++) { osum[f][nf][i] = 0.f; acc[f][nf][i] = 0.f; }

    // prologue: stages 0,1
    cp_chunk(0, sb, m0, n0);
    CP_COMMIT;
    cp_chunk(1, sb + STAGE_BYTES, m0, n0);
    CP_COMMIT;

#pragma unroll 1
    for (int cc = 0; cc < 12; cc++) {
        if (cc < 11) { CP_WAIT1; } else { CP_WAIT0; }
        __syncthreads();
        if (cc + 2 < 12) {
            cp_chunk(cc + 2, sb + (uint32_t)((cc + 2) % 3) * STAGE_BYTES, m0, n0);
            CP_COMMIT;
        }
        const uint32_t stg = sb + (uint32_t)(cc % 3) * STAGE_BYTES;
        const uint32_t AHb = stg, ALb = stg + TILE_BYTES;
        const uint32_t BHb = stg + 2 * TILE_BYTES, BLb = stg + 3 * TILE_BYTES;
#pragma unroll
        for (int ks = 0; ks < 4; ks++) {
            uint32_t ah[2][4], al[2][4];
#pragma unroll
            for (int f = 0; f < 2; f++) {
                uint32_t ao = (uint32_t)(((mbase + f * 16 + a_row) * PCH +
                                          ks * 16 + a_kof) * 2);
                ldsm_x4(ah[f], AHb + ao);
                ldsm_x4(al[f], ALb + ao);
            }
#pragma unroll
            for (int pf = 0; pf < 2; pf++) {
                uint32_t bh[4], bl[4];
                uint32_t bo = (uint32_t)(((nbase + pf * 16 + b_row) * PCH +
                                          ks * 16 + b_kof) * 2);
                ldsm_x4(bh, BHb + bo);
                ldsm_x4(bl, BLb + bo);
#pragma unroll
                for (int f = 0; f < 2; f++) {
                    mma_bf16(acc[f][2 * pf], ah[f], bh);
                    mma_bf16(acc[f][2 * pf], ah[f], bl);
                    mma_bf16(acc[f][2 * pf], al[f], bh);
                    mma_bf16(acc[f][2 * pf + 1], ah[f], bh + 2);
                    mma_bf16(acc[f][2 * pf + 1], ah[f], bl + 2);
                    mma_bf16(acc[f][2 * pf + 1], al[f], bh + 2);
                }
            }
        }
        if ((cc & 3) == 3) {  // end of one GEMM: fold tanh, reset acc
#pragma unroll
            for (int f = 0; f < 2; f++)
#pragma unroll
                for (int nf = 0; nf < 4; nf++)
#pragma unroll
                    for (int i = 0; i < 4; i++) {
                        osum[f][nf][i] += tanhf(acc[f][nf][i]);
                        acc[f][nf][i] = 0.f;
                    }
        }
    }

    const int r0 = m0 + mbase + (lane >> 2);
    const int cb = n0 + nbase + (lane & 3) * 2;
#pragma unroll
    for (int f = 0; f < 2; f++)
#pragma unroll
        for (int hh = 0; hh < 2; hh++) {
            int row = r0 + f * 16 + hh * 8;
            if (row < N) {
#pragma unroll
                for (int nf = 0; nf < 4; nf++) {
                    int col = cb + nf * 8;
                    float2 ev = *reinterpret_cast<const float2*>(
                        ent + (size_t)row * H + col);
                    float2 o = make_float2(ev.x + osum[f][nf][2 * hh],
                                           ev.y + osum[f][nf][2 * hh + 1]);
                    *reinterpret_cast<float2*>(out + (size_t)row * H + col) = o;
                }
            }
        }
}

// ---------------------------------------------------------------- out_rel = rel_emb @ rel_w
// 16 rel rows per block; each rel_w column load is reused 16x.
__global__ __launch_bounds__(256) void k_rel2(const float* __restrict__ rel,
                                              const float* __restrict__ rw,
                                              float* __restrict__ out, int R2) {
    __shared__ float rr[16][H];
    const int r0 = blockIdx.x * 16;
    const int tid = threadIdx.x;
#pragma unroll
    for (int q = 0; q < 16; q++) {
        int idx = q * 256 + tid;
        int ri = idx >> 8, ci = idx & 255;
        rr[ri][ci] = (r0 + ri < R2) ? rel[(size_t)(r0 + ri) * H + ci] : 0.f;
    }
    __syncthreads();
    float acc[16];
#pragma unroll
    for (int i = 0; i < 16; i++) acc[i] = 0.f;
#pragma unroll 4
    for (int k = 0; k < H; k++) {
        float wv = rw[(size_t)k * H + tid];
#pragma unroll
        for (int i = 0; i < 16; i++) acc[i] += rr[i][k] * wv;
    }
#pragma unroll
    for (int i = 0; i < 16; i++)
        if (r0 + i < R2) out[(size_t)(r0 + i) * H + tid] = acc[i];
}

// ---------------------------------------------------------------- launch
extern "C" void kernel_launch(void* const* d_in, const int* in_sizes, int n_in,
                              void* d_out, int out_size) {
    const float* ent    = (const float*)d_in[0];
    const float* rel    = (const float*)d_in[1];
    const float* w_edge = (const float*)d_in[2];
    const float* w_node = (const float*)d_in[3];
    const float* w_comp = (const float*)d_in[4];
    const float* rel_w  = (const float*)d_in[5];
    const int* src = (const int*)d_in[6];
    const int* dst = (const int*)d_in[7];
    const int* rid = (const int*)d_in[8];
    const int* nid = (const int*)d_in[9];
    const int N  = in_sizes[0] / H;
    const int R2 = in_sizes[1] / H;
    const int E  = in_sizes[6];
    float* out_ent = (float*)d_out;
    float* out_rel = out_ent + (size_t)N * H;

    static bool attr_set = false;
    if (!attr_set) {
        cudaFuncSetAttribute(k_gemm_mma, cudaFuncAttributeMaxDynamicSharedMemorySize,
                             GEMM_SMEM);
        attr_set = true;
    }

    const int nb_scan = (N + 1023) / 1024;
    k_wconv<<<(3 * H * H + 255) / 256, 256>>>(w_edge, w_node, w_comp);
    k_zero<<<(N + 255) / 256, 256>>>(N);
    k_hist<<<(E + 255) / 256, 256>>>(dst, E);
    k_scan_block<<<nb_scan, 1024>>>(N);
    k_scan_top<<<1, 32>>>(nb_scan);
    k_scan_add<<<(N + 255) / 256, 256>>>(N);
    k_permute<<<(E + 255) / 256, 256>>>(dst, E);
    k_edge<<<(N + 7) / 8, 256>>>(ent, rel, src, rid, nid, N);
    dim3 gg(2, (N + 127) / 128);
    k_gemm_mma<<<gg, 512, GEMM_SMEM>>>(ent, out_ent, N);
    if (R2 > 0) k_rel2<<<(R2 + 15) / 16, 256>>>(rel, rel_w, out_rel, R2);
}

// round 10
// speedup vs baseline: 1.0513x; 1.0513x over previous
#include <cuda_runtime.h>
#include <cuda_bf16.h>
#include <cstdint>

#define H 256
#define NMAX 100000
#define NPAD 100096
#define EMAX 320000

// ---------------- scratch (__device__ globals; no allocation allowed) --------
__device__ unsigned short g_ah[3][NPAD * H];    // agg rows, bf16 hi (row-major [m][k])
__device__ unsigned short g_al[3][NPAD * H];    // agg rows, bf16 lo
__device__ unsigned short g_wh[3][H * H];       // W^T hi (bf16 bits), [n][k]
__device__ unsigned short g_wl[3][H * H];       // W^T lo (bf16 bits)
__device__ int            g_deg[NMAX];
__device__ int            g_off[NMAX];
__device__ int            g_cur[NMAX];
__device__ int            g_eid[EMAX];
__device__ int            g_bsum[128];

// ---------------- helpers ----------------------------------------------------
__device__ __forceinline__ uint32_t smem_u32(const void* p) {
    uint32_t a;
    asm("{ .reg .u64 t; cvta.to.shared.u64 t, %1; cvt.u32.u64 %0, t; }"
        : "=r"(a) : "l"(p));
    return a;
}
__device__ __forceinline__ void ldsm_x4(uint32_t r[4], uint32_t addr) {
    asm volatile("ldmatrix.sync.aligned.m8n8.x4.shared.b16 {%0,%1,%2,%3}, [%4];"
                 : "=r"(r[0]), "=r"(r[1]), "=r"(r[2]), "=r"(r[3]) : "r"(addr));
}
__device__ __forceinline__ void mma_bf16(float d[4], const uint32_t a[4],
                                         const uint32_t b[2]) {
    asm volatile(
        "mma.sync.aligned.m16n8k16.row.col.f32.bf16.bf16.f32 "
        "{%0,%1,%2,%3}, {%4,%5,%6,%7}, {%8,%9}, {%0,%1,%2,%3};"
        : "+f"(d[0]), "+f"(d[1]), "+f"(d[2]), "+f"(d[3])
        : "r"(a[0]), "r"(a[1]), "r"(a[2]), "r"(a[3]), "r"(b[0]), "r"(b[1]));
}
__device__ __forceinline__ void cp16(uint32_t dst, const void* src) {
    asm volatile("cp.async.cg.shared.global [%0], [%1], 16;"
                 :: "r"(dst), "l"(src) : "memory");
}
#define CP_COMMIT asm volatile("cp.async.commit_group;" ::: "memory")
#define CP_WAIT0  asm volatile("cp.async.wait_group 0;" ::: "memory")
#define CP_WAIT1  asm volatile("cp.async.wait_group 1;" ::: "memory")

__device__ __forceinline__ float wsum(float v) {
#pragma unroll
    for (int o = 16; o; o >>= 1) v += __shfl_xor_sync(0xffffffffu, v, o);
    return v;
}
__device__ __forceinline__ unsigned short bf_hi(float x, float& res) {
    __nv_bfloat16 h = __float2bfloat16(x);
    res = x - __bfloat162float(h);
    return __bfloat16_as_ushort(h);
}
__device__ __forceinline__ void split_store4(unsigned short* ph, unsigned short* pl,
                                             float4 v) {
    float r0, r1, r2, r3;
    unsigned short h0 = bf_hi(v.x, r0), h1 = bf_hi(v.y, r1);
    unsigned short h2 = bf_hi(v.z, r2), h3 = bf_hi(v.w, r3);
    uint2 hh, ll;
    hh.x = ((uint32_t)h1 << 16) | h0;
    hh.y = ((uint32_t)h3 << 16) | h2;
    ll.x = ((uint32_t)__bfloat16_as_ushort(__float2bfloat16(r1)) << 16) |
           __bfloat16_as_ushort(__float2bfloat16(r0));
    ll.y = ((uint32_t)__bfloat16_as_ushort(__float2bfloat16(r3)) << 16) |
           __bfloat16_as_ushort(__float2bfloat16(r2));
    __stcs(reinterpret_cast<uint2*>(ph), hh);
    __stcs(reinterpret_cast<uint2*>(pl), ll);
}

// --------------------------------- W -> W^T bf16 hi/lo split + CSR zero (fused)
__global__ void k_wz(const float* __restrict__ w0, const float* __restrict__ w1,
                     const float* __restrict__ w2, int N) {
    int i = blockIdx.x * blockDim.x + threadIdx.x;
    if (i < 3 * H * H) {
        int g = i >> 16;
        int r = i & 0xFFFF;
        int k = r >> 8, n = r & 255;
        const float* w = (g == 0) ? w0 : (g == 1) ? w1 : w2;
        float v = w[k * H + n];
        float lo;
        unsigned short hi = bf_hi(v, lo);
        g_wh[g][n * H + k] = hi;
        g_wl[g][n * H + k] = __bfloat16_as_ushort(__float2bfloat16(lo));
    }
    int j = i - 3 * H * H;
    if (j >= 0 && j < N) { g_deg[j] = 0; g_cur[j] = 0; }
}

// ---------------------------------------------------------------- CSR build
__global__ void k_hist(const int* __restrict__ dst, int E) {
    int e = blockIdx.x * blockDim.x + threadIdx.x;
    if (e < E) atomicAdd(&g_deg[dst[e]], 1);
}
__global__ void k_scan_block(int N) {
    __shared__ int sm[1024];
    int tid = threadIdx.x;
    int i = blockIdx.x * 1024 + tid;
    int v = (i < N) ? g_deg[i] : 0;
    sm[tid] = v;
    __syncthreads();
#pragma unroll
    for (int o = 1; o < 1024; o <<= 1) {
        int t = (tid >= o) ? sm[tid - o] : 0;
        __syncthreads();
        sm[tid] += t;
        __syncthreads();
    }
    if (i < N) g_off[i] = sm[tid] - v;  // exclusive
    if (tid == 1023) g_bsum[blockIdx.x] = sm[1023];
}
__global__ void k_scan_top(int nb) {
    if (threadIdx.x == 0 && blockIdx.x == 0) {
        int run = 0;
        for (int b = 0; b < nb; b++) { int t = g_bsum[b]; g_bsum[b] = run; run += t; }
    }
}
__global__ void k_scan_add(int N) {
    int i = blockIdx.x * blockDim.x + threadIdx.x;
    if (i < N) g_off[i] += g_bsum[i >> 10];
}
__global__ void k_permute(const int* __restrict__ dst, int E) {
    int e = blockIdx.x * blockDim.x + threadIdx.x;
    if (e >= E) return;
    int d = dst[e];
    int slot = g_off[d] + atomicAdd(&g_cur[d], 1);
    g_eid[slot] = e;
}

// ------------------------------------------ fused edge pass: warp per dst node
__global__ __launch_bounds__(256) void k_edge(
    const float* __restrict__ ent, const float* __restrict__ rel,
    const int* __restrict__ src, const int* __restrict__ rid,
    const int* __restrict__ nid, int N) {
    int w = (blockIdx.x * 256 + threadIdx.x) >> 5;
    if (w >= N) return;
    const int lane = threadIdx.x & 31;
    const int d = w;
    const int dn = nid[d];
    const float4* ent4 = reinterpret_cast<const float4*>(ent);
    const float4* rel4 = reinterpret_cast<const float4*>(rel);
    const float4 hda = ent4[(size_t)dn * 64 + lane];
    const float4 hdb = ent4[(size_t)dn * 64 + lane + 32];

    const int off0 = g_off[d];
    const int deg = g_deg[d];

    float m0 = -1e30f, m1 = -1e30f, m2 = -1e30f;
    float s0 = 0.f, s1 = 0.f, s2 = 0.f;
    float4 a0a = {0, 0, 0, 0}, a0b = {0, 0, 0, 0};
    float4 a1a = {0, 0, 0, 0}, a1b = {0, 0, 0, 0};
    float4 a2a = {0, 0, 0, 0}, a2b = {0, 0, 0, 0};

    // index prefetch: start next edge's pointer chase before current compute
    int sn_n = 0, rr_n = 0;
    if (deg > 0) {
        int e0 = g_eid[off0];
        sn_n = nid[src[e0]];
        rr_n = rid[e0];
    }
    for (int j = 0; j < deg; j++) {
        int sn = sn_n, rr = rr_n;
        if (j + 1 < deg) {
            int e1 = g_eid[off0 + j + 1];
            sn_n = nid[src[e1]];
            rr_n = rid[e1];
        }
        float4 sa = ent4[(size_t)sn * 64 + lane];
        float4 sb = ent4[(size_t)sn * 64 + lane + 32];
        float4 ea = rel4[(size_t)rr * 64 + lane];
        float4 eb = rel4[(size_t)rr * 64 + lane + 32];
        float pe = ea.x * hda.x + ea.y * hda.y + ea.z * hda.z + ea.w * hda.w
                 + eb.x * hdb.x + eb.y * hdb.y + eb.z * hdb.z + eb.w * hdb.w;
        float pn = sa.x * hda.x + sa.y * hda.y + sa.z * hda.z + sa.w * hda.w
                 + sb.x * hdb.x + sb.y * hdb.y + sb.z * hdb.z + sb.w * hdb.w;
        float pc = sa.x * ea.x * hda.x + sa.y * ea.y * hda.y
                 + sa.z * ea.z * hda.z + sa.w * ea.w * hda.w
                 + sb.x * eb.x * hdb.x + sb.y * eb.y * hdb.y
                 + sb.z * eb.z * hdb.z + sb.w * eb.w * hdb.w;
        float de = wsum(pe), dn_ = wsum(pn), dc = wsum(pc);
        float nm0 = fmaxf(m0, de), c0 = expf(m0 - nm0), w0 = expf(de - nm0);
        float nm1 = fmaxf(m1, dn_), c1 = expf(m1 - nm1), w1 = expf(dn_ - nm1);
        float nm2 = fmaxf(m2, dc), c2 = expf(m2 - nm2), w2 = expf(dc - nm2);
        m0 = nm0; m1 = nm1; m2 = nm2;
        s0 = s0 * c0 + w0; s1 = s1 * c1 + w1; s2 = s2 * c2 + w2;
        a0a.x = a0a.x * c0 + ea.x * w0; a0a.y = a0a.y * c0 + ea.y * w0;
        a0a.z = a0a.z * c0 + ea.z * w0; a0a.w = a0a.w * c0 + ea.w * w0;
        a0b.x = a0b.x * c0 + eb.x * w0; a0b.y = a0b.y * c0 + eb.y * w0;
        a0b.z = a0b.z * c0 + eb.z * w0; a0b.w = a0b.w * c0 + eb.w * w0;
        a1a.x = a1a.x * c1 + sa.x * w1; a1a.y = a1a.y * c1 + sa.y * w1;
        a1a.z = a1a.z * c1 + sa.z * w1; a1a.w = a1a.w * c1 + sa.w * w1;
        a1b.x = a1b.x * c1 + sb.x * w1; a1b.y = a1b.y * c1 + sb.y * w1;
        a1b.z = a1b.z * c1 + sb.z * w1; a1b.w = a1b.w * c1 + sb.w * w1;
        a2a.x = a2a.x * c2 + sa.x * ea.x * w2; a2a.y = a2a.y * c2 + sa.y * ea.y * w2;
        a2a.z = a2a.z * c2 + sa.z * ea.z * w2; a2a.w = a2a.w * c2 + sa.w * ea.w * w2;
        a2b.x = a2b.x * c2 + sb.x * eb.x * w2; a2b.y = a2b.y * c2 + sb.y * eb.y * w2;
        a2b.z = a2b.z * c2 + sb.z * eb.z * w2; a2b.w = a2b.w * c2 + sb.w * eb.w * w2;
    }
    float i0 = (s0 > 0.f) ? 1.f / s0 : 0.f;
    float i1 = (s1 > 0.f) ? 1.f / s1 : 0.f;
    float i2 = (s2 > 0.f) ? 1.f / s2 : 0.f;
    size_t base = (size_t)d * H + 4 * lane;
    split_store4(g_ah[0] + base, g_al[0] + base,
                 make_float4(a0a.x * i0, a0a.y * i0, a0a.z * i0, a0a.w * i0));
    split_store4(g_ah[0] + base + 128, g_al[0] + base + 128,
                 make_float4(a0b.x * i0, a0b.y * i0, a0b.z * i0, a0b.w * i0));
    split_store4(g_ah[1] + base, g_al[1] + base,
                 make_float4(a1a.x * i1, a1a.y * i1, a1a.z * i1, a1a.w * i1));
    split_store4(g_ah[1] + base + 128, g_al[1] + base + 128,
                 make_float4(a1b.x * i1, a1b.y * i1, a1b.z * i1, a1b.w * i1));
    split_store4(g_ah[2] + base, g_al[2] + base,
                 make_float4(a2a.x * i2, a2a.y * i2, a2a.z * i2, a2a.w * i2));
    split_store4(g_ah[2] + base + 128, g_al[2] + base + 128,
                 make_float4(a2b.x * i2, a2b.y * i2, a2b.z * i2, a2b.w * i2));
}

// ---------------------------------------------------------------- mma.sync split-bf16 GEMM
// CTA: 128x128 tile; 512 threads = 16 warps (4m x 4n), warp tile 32x32.
// 12 flattened chunks (3 g x 4 k-chunks), 3-stage cp.async pipeline.
// MMA issue order grouped by split pass: 8 independent accumulators between
// consecutive touches of any acc reg (kills the HMMA RAW stall chain).
#define PCH 72                               // smem pitch (bf16 elems) = 144 B
#define KC 64
#define TILE_BYTES (128 * PCH * 2)           // 18432
#define STAGE_BYTES (4 * TILE_BYTES)         // Ah | Al | Bh | Bl = 73728
#define GEMM_SMEM (3 * STAGE_BYTES)          // 221184

__device__ __forceinline__ void cp_chunk(int cc, uint32_t stg, int m0, int n0) {
    const int g = cc >> 2, c = cc & 3;
    const int k0 = c * KC;
    const int tid = threadIdx.x;
#pragma unroll
    for (int q = 0; q < 2; q++) {
        int idx = q * 512 + tid;
        int row = idx >> 3, oct = idx & 7;
        uint32_t off = (uint32_t)(row * (PCH * 2) + oct * 16);
        size_t gi = (size_t)(m0 + row) * H + k0 + oct * 8;
        cp16(stg + off, g_ah[g] + gi);
        cp16(stg + TILE_BYTES + off, g_al[g] + gi);
    }
#pragma unroll
    for (int q = 0; q < 2; q++) {
        int idx = q * 512 + tid;
        int row = idx >> 3, oct = idx & 7;
        uint32_t off = (uint32_t)(row * (PCH * 2) + oct * 16);
        size_t gi = (size_t)(n0 + row) * H + k0 + oct * 8;
        cp16(stg + 2 * TILE_BYTES + off, g_wh[g] + gi);
        cp16(stg + 3 * TILE_BYTES + off, g_wl[g] + gi);
    }
}

__global__ __launch_bounds__(512, 1)
void k_gemm_mma(const float* __restrict__ ent, float* __restrict__ out, int N) {
    extern __shared__ char smem[];
    const uint32_t sb = smem_u32(smem);
    const int tid = threadIdx.x;
    const int lane = tid & 31, wid = tid >> 5;
    const int wm = wid >> 2, wn = wid & 3;
    const int mbase = wm * 32, nbase = wn * 32;
    const int m0 = blockIdx.y * 128, n0 = blockIdx.x * 128;

    const int a_row = (lane & 7) + ((lane >> 3) & 1) * 8;
    const int a_kof = (lane >> 4) * 8;
    const int b_row = (lane & 7) + (lane >> 4) * 8;
    const int b_kof = ((lane >> 3) & 1) * 8;

    float osum[2][4][4], acc[2][4][4];
#pragma unroll
    for (int f = 0; f < 2; f++)
#pragma unroll
        for (int nf = 0; nf < 4; nf++)
#pragma unroll
            for (int i = 0; i < 4; i++) { osum[f][nf][i] = 0.f; acc[f][nf][i] = 0.f; }

    // prologue: stages 0,1
    cp_chunk(0, sb, m0, n0);
    CP_COMMIT;
    cp_chunk(1, sb + STAGE_BYTES, m0, n0);
    CP_COMMIT;

#pragma unroll 1
    for (int cc = 0; cc < 12; cc++) {
        if (cc < 11) { CP_WAIT1; } else { CP_WAIT0; }
        __syncthreads();
        if (cc + 2 < 12) {
            cp_chunk(cc + 2, sb + (uint32_t)((cc + 2) % 3) * STAGE_BYTES, m0, n0);
            CP_COMMIT;
        }
        const uint32_t stg = sb + (uint32_t)(cc % 3) * STAGE_BYTES;
        const uint32_t AHb = stg, ALb = stg + TILE_BYTES;
        const uint32_t BHb = stg + 2 * TILE_BYTES, BLb = stg + 3 * TILE_BYTES;
#pragma unroll
        for (int ks = 0; ks < 4; ks++) {
            uint32_t ah[2][4], al[2][4], bh[2][4], bl[2][4];
#pragma unroll
            for (int f = 0; f < 2; f++) {
                uint32_t ao = (uint32_t)(((mbase + f * 16 + a_row) * PCH +
                                          ks * 16 + a_kof) * 2);
                ldsm_x4(ah[f], AHb + ao);
                ldsm_x4(al[f], ALb + ao);
            }
#pragma unroll
            for (int pf = 0; pf < 2; pf++) {
                uint32_t bo = (uint32_t)(((nbase + pf * 16 + b_row) * PCH +
                                          ks * 16 + b_kof) * 2);
                ldsm_x4(bh[pf], BHb + bo);
                ldsm_x4(bl[pf], BLb + bo);
            }
            // pass 1: Ah x Bh  (8 independent accumulators)
#pragma unroll
            for (int f = 0; f < 2; f++)
#pragma unroll
                for (int pf = 0; pf < 2; pf++) {
                    mma_bf16(acc[f][2 * pf],     ah[f], bh[pf]);
                    mma_bf16(acc[f][2 * pf + 1], ah[f], bh[pf] + 2);
                }
            // pass 2: Ah x Bl
#pragma unroll
            for (int f = 0; f < 2; f++)
#pragma unroll
                for (int pf = 0; pf < 2; pf++) {
                    mma_bf16(acc[f][2 * pf],     ah[f], bl[pf]);
                    mma_bf16(acc[f][2 * pf + 1], ah[f], bl[pf] + 2);
                }
            // pass 3: Al x Bh
#pragma unroll
            for (int f = 0; f < 2; f++)
#pragma unroll
                for (int pf = 0; pf < 2; pf++) {
                    mma_bf16(acc[f][2 * pf],     al[f], bh[pf]);
                    mma_bf16(acc[f][2 * pf + 1], al[f], bh[pf] + 2);
                }
        }
        if ((cc & 3) == 3) {  // end of one GEMM: fold tanh, reset acc
#pragma unroll
            for (int f = 0; f < 2; f++)
#pragma unroll
                for (int nf = 0; nf < 4; nf++)
#pragma unroll
                    for (int i = 0; i < 4; i++) {
                        osum[f][nf][i] += tanhf(acc[f][nf][i]);
                        acc[f][nf][i] = 0.f;
                    }
        }
    }

    const int r0 = m0 + mbase + (lane >> 2);
    const int cb = n0 + nbase + (lane & 3) * 2;
#pragma unroll
    for (int f = 0; f < 2; f++)
#pragma unroll
        for (int hh = 0; hh < 2; hh++) {
            int row = r0 + f * 16 + hh * 8;
            if (row < N) {
#pragma unroll
                for (int nf = 0; nf < 4; nf++) {
                    int col = cb + nf * 8;
                    float2 ev = *reinterpret_cast<const float2*>(
                        ent + (size_t)row * H + col);
                    float2 o = make_float2(ev.x + osum[f][nf][2 * hh],
                                           ev.y + osum[f][nf][2 * hh + 1]);
                    *reinterpret_cast<float2*>(out + (size_t)row * H + col) = o;
                }
            }
        }
}

// ---------------------------------------------------------------- out_rel = rel_emb @ rel_w
__global__ __launch_bounds__(256) void k_rel2(const float* __restrict__ rel,
                                              const float* __restrict__ rw,
                                              float* __restrict__ out, int R2) {
    __shared__ float rr[16][H];
    const int r0 = blockIdx.x * 16;
    const int tid = threadIdx.x;
#pragma unroll
    for (int q = 0; q < 16; q++) {
        int idx = q * 256 + tid;
        int ri = idx >> 8, ci = idx & 255;
        rr[ri][ci] = (r0 + ri < R2) ? rel[(size_t)(r0 + ri) * H + ci] : 0.f;
    }
    __syncthreads();
    float acc[16];
#pragma unroll
    for (int i = 0; i < 16; i++) acc[i] = 0.f;
#pragma unroll 4
    for (int k = 0; k < H; k++) {
        float wv = rw[(size_t)k * H + tid];
#pragma unroll
        for (int i = 0; i < 16; i++) acc[i] += rr[i][k] * wv;
    }
#pragma unroll
    for (int i = 0; i < 16; i++)
        if (r0 + i < R2) out[(size_t)(r0 + i) * H + tid] = acc[i];
}

// ---------------------------------------------------------------- launch
extern "C" void kernel_launch(void* const* d_in, const int* in_sizes, int n_in,
                              void* d_out, int out_size) {
    const float* ent    = (const float*)d_in[0];
    const float* rel    = (const float*)d_in[1];
    const float* w_edge = (const float*)d_in[2];
    const float* w_node = (const float*)d_in[3];
    const float* w_comp = (const float*)d_in[4];
    const float* rel_w  = (const float*)d_in[5];
    const int* src = (const int*)d_in[6];
    const int* dst = (const int*)d_in[7];
    const int* rid = (const int*)d_in[8];
    const int* nid = (const int*)d_in[9];
    const int N  = in_sizes[0] / H;
    const int R2 = in_sizes[1] / H;
    const int E  = in_sizes[6];
    float* out_ent = (float*)d_out;
    float* out_rel = out_ent + (size_t)N * H;

    static bool attr_set = false;
    if (!attr_set) {
        cudaFuncSetAttribute(k_gemm_mma, cudaFuncAttributeMaxDynamicSharedMemorySize,
                             GEMM_SMEM);
        attr_set = true;
    }

    const int nb_scan = (N + 1023) / 1024;
    k_wz<<<(3 * H * H + N + 255) / 256, 256>>>(w_edge, w_node, w_comp, N);
    k_hist<<<(E + 255) / 256, 256>>>(dst, E);
    k_scan_block<<<nb_scan, 1024>>>(N);
    k_scan_top<<<1, 32>>>(nb_scan);
    k_scan_add<<<(N + 255) / 256, 256>>>(N);
    k_permute<<<(E + 255) / 256, 256>>>(dst, E);
    k_edge<<<(N + 7) / 8, 256>>>(ent, rel, src, rid, nid, N);
    dim3 gg(2, (N + 127) / 128);
    k_gemm_mma<<<gg, 512, GEMM_SMEM>>>(ent, out_ent, N);
    if (R2 > 0) k_rel2<<<(R2 + 15) / 16, 256>>>(rel, rel_w, out_rel, R2);
}

// round 11
// speedup vs baseline: 1.1541x; 1.0977x over previous
#include <cuda_runtime.h>
#include <cuda_bf16.h>
#include <cstdint>

#define H 256
#define NMAX 100000
#define NPAD 100096
#define EMAX 320000

// ---------------- scratch (__device__ globals; no allocation allowed) --------
__device__ float g_agg[3][NPAD * H];   // agg rows, fp32 pre-rounded to tf32
__device__ float g_wt[3][H * H];       // W^T, fp32 pre-rounded to tf32, [n][k]
__device__ int   g_deg[NMAX];
__device__ int   g_off[NMAX];
__device__ int   g_cur[NMAX];
__device__ int   g_eid[EMAX];
__device__ int   g_bsum[128];

// ---------------- helpers ----------------------------------------------------
__device__ __forceinline__ uint32_t smem_u32(const void* p) {
    uint32_t a;
    asm("{ .reg .u64 t; cvta.to.shared.u64 t, %1; cvt.u32.u64 %0, t; }"
        : "=r"(a) : "l"(p));
    return a;
}
__device__ __forceinline__ float tf32r(float x) {
    uint32_t u;
    asm("cvt.rna.tf32.f32 %0, %1;" : "=r"(u) : "f"(x));
    return __uint_as_float(u);
}
__device__ __forceinline__ void ldsm_x4(uint32_t r[4], uint32_t addr) {
    asm volatile("ldmatrix.sync.aligned.m8n8.x4.shared.b16 {%0,%1,%2,%3}, [%4];"
                 : "=r"(r[0]), "=r"(r[1]), "=r"(r[2]), "=r"(r[3]) : "r"(addr));
}
__device__ __forceinline__ void mma_tf32(float d[4], const uint32_t a[4],
                                         const uint32_t b[2]) {
    asm volatile(
        "mma.sync.aligned.m16n8k8.row.col.f32.tf32.tf32.f32 "
        "{%0,%1,%2,%3}, {%4,%5,%6,%7}, {%8,%9}, {%0,%1,%2,%3};"
        : "+f"(d[0]), "+f"(d[1]), "+f"(d[2]), "+f"(d[3])
        : "r"(a[0]), "r"(a[1]), "r"(a[2]), "r"(a[3]), "r"(b[0]), "r"(b[1]));
}
__device__ __forceinline__ void cp16(uint32_t dst, const void* src) {
    asm volatile("cp.async.cg.shared.global [%0], [%1], 16;"
                 :: "r"(dst), "l"(src) : "memory");
}
#define CP_COMMIT asm volatile("cp.async.commit_group;" ::: "memory")
#define CP_WAIT0  asm volatile("cp.async.wait_group 0;" ::: "memory")
#define CP_WAIT1  asm volatile("cp.async.wait_group 1;" ::: "memory")

__device__ __forceinline__ float wsum(float v) {
#pragma unroll
    for (int o = 16; o; o >>= 1) v += __shfl_xor_sync(0xffffffffu, v, o);
    return v;
}

// --------------------------------- W -> W^T tf32 + CSR zero (fused)
__global__ void k_wz(const float* __restrict__ w0, const float* __restrict__ w1,
                     const float* __restrict__ w2, int N) {
    int i = blockIdx.x * blockDim.x + threadIdx.x;
    if (i < 3 * H * H) {
        int g = i >> 16;
        int r = i & 0xFFFF;
        int k = r >> 8, n = r & 255;
        const float* w = (g == 0) ? w0 : (g == 1) ? w1 : w2;
        g_wt[g][n * H + k] = tf32r(w[k * H + n]);
    }
    int j = i - 3 * H * H;
    if (j >= 0 && j < N) { g_deg[j] = 0; g_cur[j] = 0; }
}

// ---------------------------------------------------------------- CSR build
__global__ void k_hist(const int* __restrict__ dst, int E) {
    int e = blockIdx.x * blockDim.x + threadIdx.x;
    if (e < E) atomicAdd(&g_deg[dst[e]], 1);
}
__global__ void k_scan_block(int N) {
    __shared__ int sm[1024];
    int tid = threadIdx.x;
    int i = blockIdx.x * 1024 + tid;
    int v = (i < N) ? g_deg[i] : 0;
    sm[tid] = v;
    __syncthreads();
#pragma unroll
    for (int o = 1; o < 1024; o <<= 1) {
        int t = (tid >= o) ? sm[tid - o] : 0;
        __syncthreads();
        sm[tid] += t;
        __syncthreads();
    }
    if (i < N) g_off[i] = sm[tid] - v;  // exclusive
    if (tid == 1023) g_bsum[blockIdx.x] = sm[1023];
}
__global__ void k_scan_top(int nb) {
    if (threadIdx.x == 0 && blockIdx.x == 0) {
        int run = 0;
        for (int b = 0; b < nb; b++) { int t = g_bsum[b]; g_bsum[b] = run; run += t; }
    }
}
__global__ void k_scan_add(int N) {
    int i = blockIdx.x * blockDim.x + threadIdx.x;
    if (i < N) g_off[i] += g_bsum[i >> 10];
}
__global__ void k_permute(const int* __restrict__ dst, int E) {
    int e = blockIdx.x * blockDim.x + threadIdx.x;
    if (e >= E) return;
    int d = dst[e];
    int slot = g_off[d] + atomicAdd(&g_cur[d], 1);
    g_eid[slot] = e;
}

// ------------------------------------------ fused edge pass: warp per dst node
__global__ __launch_bounds__(256) void k_edge(
    const float* __restrict__ ent, const float* __restrict__ rel,
    const int* __restrict__ src, const int* __restrict__ rid,
    const int* __restrict__ nid, int N) {
    int w = (blockIdx.x * 256 + threadIdx.x) >> 5;
    if (w >= N) return;
    const int lane = threadIdx.x & 31;
    const int d = w;
    const int dn = nid[d];
    const float4* ent4 = reinterpret_cast<const float4*>(ent);
    const float4* rel4 = reinterpret_cast<const float4*>(rel);
    const float4 hda = ent4[(size_t)dn * 64 + lane];
    const float4 hdb = ent4[(size_t)dn * 64 + lane + 32];

    const int off0 = g_off[d];
    const int deg = g_deg[d];

    float m0 = -1e30f, m1 = -1e30f, m2 = -1e30f;
    float s0 = 0.f, s1 = 0.f, s2 = 0.f;
    float4 a0a = {0, 0, 0, 0}, a0b = {0, 0, 0, 0};
    float4 a1a = {0, 0, 0, 0}, a1b = {0, 0, 0, 0};
    float4 a2a = {0, 0, 0, 0}, a2b = {0, 0, 0, 0};

    int sn_n = 0, rr_n = 0;
    if (deg > 0) {
        int e0 = g_eid[off0];
        sn_n = nid[src[e0]];
        rr_n = rid[e0];
    }
    for (int j = 0; j < deg; j++) {
        int sn = sn_n, rr = rr_n;
        if (j + 1 < deg) {
            int e1 = g_eid[off0 + j + 1];
            sn_n = nid[src[e1]];
            rr_n = rid[e1];
        }
        float4 sa = ent4[(size_t)sn * 64 + lane];
        float4 sb = ent4[(size_t)sn * 64 + lane + 32];
        float4 ea = rel4[(size_t)rr * 64 + lane];
        float4 eb = rel4[(size_t)rr * 64 + lane + 32];
        float pe = ea.x * hda.x + ea.y * hda.y + ea.z * hda.z + ea.w * hda.w
                 + eb.x * hdb.x + eb.y * hdb.y + eb.z * hdb.z + eb.w * hdb.w;
        float pn = sa.x * hda.x + sa.y * hda.y + sa.z * hda.z + sa.w * hda.w
                 + sb.x * hdb.x + sb.y * hdb.y + sb.z * hdb.z + sb.w * hdb.w;
        float pc = sa.x * ea.x * hda.x + sa.y * ea.y * hda.y
                 + sa.z * ea.z * hda.z + sa.w * ea.w * hda.w
                 + sb.x * eb.x * hdb.x + sb.y * eb.y * hdb.y
                 + sb.z * eb.z * hdb.z + sb.w * eb.w * hdb.w;
        float de = wsum(pe), dn_ = wsum(pn), dc = wsum(pc);
        float nm0 = fmaxf(m0, de), c0 = expf(m0 - nm0), w0 = expf(de - nm0);
        float nm1 = fmaxf(m1, dn_), c1 = expf(m1 - nm1), w1 = expf(dn_ - nm1);
        float nm2 = fmaxf(m2, dc), c2 = expf(m2 - nm2), w2 = expf(dc - nm2);
        m0 = nm0; m1 = nm1; m2 = nm2;
        s0 = s0 * c0 + w0; s1 = s1 * c1 + w1; s2 = s2 * c2 + w2;
        a0a.x = a0a.x * c0 + ea.x * w0; a0a.y = a0a.y * c0 + ea.y * w0;
        a0a.z = a0a.z * c0 + ea.z * w0; a0a.w = a0a.w * c0 + ea.w * w0;
        a0b.x = a0b.x * c0 + eb.x * w0; a0b.y = a0b.y * c0 + eb.y * w0;
        a0b.z = a0b.z * c0 + eb.z * w0; a0b.w = a0b.w * c0 + eb.w * w0;
        a1a.x = a1a.x * c1 + sa.x * w1; a1a.y = a1a.y * c1 + sa.y * w1;
        a1a.z = a1a.z * c1 + sa.z * w1; a1a.w = a1a.w * c1 + sa.w * w1;
        a1b.x = a1b.x * c1 + sb.x * w1; a1b.y = a1b.y * c1 + sb.y * w1;
        a1b.z = a1b.z * c1 + sb.z * w1; a1b.w = a1b.w * c1 + sb.w * w1;
        a2a.x = a2a.x * c2 + sa.x * ea.x * w2; a2a.y = a2a.y * c2 + sa.y * ea.y * w2;
        a2a.z = a2a.z * c2 + sa.z * ea.z * w2; a2a.w = a2a.w * c2 + sa.w * ea.w * w2;
        a2b.x = a2b.x * c2 + sb.x * eb.x * w2; a2b.y = a2b.y * c2 + sb.y * eb.y * w2;
        a2b.z = a2b.z * c2 + sb.z * eb.z * w2; a2b.w = a2b.w * c2 + sb.w * eb.w * w2;
    }
    float i0 = (s0 > 0.f) ? 1.f / s0 : 0.f;
    float i1 = (s1 > 0.f) ? 1.f / s1 : 0.f;
    float i2 = (s2 > 0.f) ? 1.f / s2 : 0.f;
    float* r0 = g_agg[0] + (size_t)d * H + 4 * lane;
    float* r1 = g_agg[1] + (size_t)d * H + 4 * lane;
    float* r2 = g_agg[2] + (size_t)d * H + 4 * lane;
    __stcs(reinterpret_cast<float4*>(r0),
           make_float4(tf32r(a0a.x * i0), tf32r(a0a.y * i0),
                       tf32r(a0a.z * i0), tf32r(a0a.w * i0)));
    __stcs(reinterpret_cast<float4*>(r0 + 128),
           make_float4(tf32r(a0b.x * i0), tf32r(a0b.y * i0),
                       tf32r(a0b.z * i0), tf32r(a0b.w * i0)));
    __stcs(reinterpret_cast<float4*>(r1),
           make_float4(tf32r(a1a.x * i1), tf32r(a1a.y * i1),
                       tf32r(a1a.z * i1), tf32r(a1a.w * i1)));
    __stcs(reinterpret_cast<float4*>(r1 + 128),
           make_float4(tf32r(a1b.x * i1), tf32r(a1b.y * i1),
                       tf32r(a1b.z * i1), tf32r(a1b.w * i1)));
    __stcs(reinterpret_cast<float4*>(r2),
           make_float4(tf32r(a2a.x * i2), tf32r(a2a.y * i2),
                       tf32r(a2a.z * i2), tf32r(a2a.w * i2)));
    __stcs(reinterpret_cast<float4*>(r2 + 128),
           make_float4(tf32r(a2b.x * i2), tf32r(a2b.y * i2),
                       tf32r(a2b.z * i2), tf32r(a2b.w * i2)));
}

// ---------------------------------------------------------------- tf32 GEMM
// CTA: 128x128 tile; 512 threads = 16 warps (4m x 4n), warp tile 32x32.
// 24 flattened chunks (3 g x 8 k-chunks of 32), 3-stage cp.async pipeline.
// Single-pass tf32 mma (data pre-rounded rna at producers).
#define PCHB 144                             // smem pitch bytes (36 f32, conflict-free)
#define KCF 32                               // k per chunk (f32)
#define TILE_BYTES (128 * PCHB)              // 18432
#define STAGE_BYTES (2 * TILE_BYTES)         // A | B = 36864
#define GEMM_SMEM (3 * STAGE_BYTES)          // 110592

__device__ __forceinline__ void cp_chunk(int cc, uint32_t stg, int m0, int n0) {
    const int g = cc >> 3, c = cc & 7;
    const int k0 = c * KCF;
    const int tid = threadIdx.x;
#pragma unroll
    for (int q = 0; q < 2; q++) {                 // A: 1024 cp16
        int idx = q * 512 + tid;
        int row = idx >> 3, oct = idx & 7;
        uint32_t off = (uint32_t)(row * PCHB + oct * 16);
        size_t gi = (size_t)(m0 + row) * H + k0 + oct * 4;
        cp16(stg + off, g_agg[g] + gi);
    }
#pragma unroll
    for (int q = 0; q < 2; q++) {                 // B: 1024 cp16
        int idx = q * 512 + tid;
        int row = idx >> 3, oct = idx & 7;
        uint32_t off = (uint32_t)(row * PCHB + oct * 16);
        size_t gi = (size_t)(n0 + row) * H + k0 + oct * 4;
        cp16(stg + TILE_BYTES + off, g_wt[g] + gi);
    }
}

__global__ __launch_bounds__(512, 1)
void k_gemm_mma(const float* __restrict__ ent, float* __restrict__ out, int N) {
    extern __shared__ char smem[];
    const uint32_t sb = smem_u32(smem);
    const int tid = threadIdx.x;
    const int lane = tid & 31, wid = tid >> 5;
    const int wm = wid >> 2, wn = wid & 3;
    const int mbase = wm * 32, nbase = wn * 32;
    const int m0 = blockIdx.y * 128, n0 = blockIdx.x * 128;

    // ldmatrix-on-fp32 per-lane addressing (byte offsets)
    const int a_row = (lane & 7) + ((lane >> 3) & 1) * 8;   // m within 16
    const int a_kofB = (lane >> 4) * 16;                    // k half (bytes)
    const int b_row = (lane & 7) + (lane >> 4) * 8;         // n within 16
    const int b_kofB = ((lane >> 3) & 1) * 16;              // k half (bytes)

    float osum[2][4][4], acc[2][4][4];
#pragma unroll
    for (int f = 0; f < 2; f++)
#pragma unroll
        for (int nf = 0; nf < 4; nf++)
#pragma unroll
            for (int i = 0; i < 4; i++) { osum[f][nf][i] = 0.f; acc[f][nf][i] = 0.f; }

    cp_chunk(0, sb, m0, n0);
    CP_COMMIT;
    cp_chunk(1, sb + STAGE_BYTES, m0, n0);
    CP_COMMIT;

#pragma unroll 1
    for (int cc = 0; cc < 24; cc++) {
        if (cc < 23) { CP_WAIT1; } else { CP_WAIT0; }
        __syncthreads();
        if (cc + 2 < 24) {
            cp_chunk(cc + 2, sb + (uint32_t)((cc + 2) % 3) * STAGE_BYTES, m0, n0);
            CP_COMMIT;
        }
        const uint32_t stg = sb + (uint32_t)(cc % 3) * STAGE_BYTES;
        const uint32_t Ab = stg, Bb = stg + TILE_BYTES;
#pragma unroll
        for (int ks = 0; ks < 4; ks++) {          // 4 k-steps of 8
            uint32_t af[2][4], bf[2][4];
#pragma unroll
            for (int f = 0; f < 2; f++) {
                uint32_t ao = (uint32_t)((mbase + f * 16 + a_row) * PCHB +
                                         ks * 32) + a_kofB;
                ldsm_x4(af[f], Ab + ao);
            }
#pragma unroll
            for (int pf = 0; pf < 2; pf++) {
                uint32_t bo = (uint32_t)((nbase + pf * 16 + b_row) * PCHB +
                                         ks * 32) + b_kofB;
                ldsm_x4(bf[pf], Bb + bo);
            }
            // 8 MMAs, 8 independent accumulators
#pragma unroll
            for (int f = 0; f < 2; f++)
#pragma unroll
                for (int pf = 0; pf < 2; pf++) {
                    mma_tf32(acc[f][2 * pf],     af[f], bf[pf]);
                    mma_tf32(acc[f][2 * pf + 1], af[f], bf[pf] + 2);
                }
        }
        if ((cc & 7) == 7) {  // end of one GEMM: fold tanh, reset acc
#pragma unroll
            for (int f = 0; f < 2; f++)
#pragma unroll
                for (int nf = 0; nf < 4; nf++)
#pragma unroll
                    for (int i = 0; i < 4; i++) {
                        osum[f][nf][i] += tanhf(acc[f][nf][i]);
                        acc[f][nf][i] = 0.f;
                    }
        }
    }

    const int r0 = m0 + mbase + (lane >> 2);
    const int cb = n0 + nbase + (lane & 3) * 2;
#pragma unroll
    for (int f = 0; f < 2; f++)
#pragma unroll
        for (int hh = 0; hh < 2; hh++) {
            int row = r0 + f * 16 + hh * 8;
            if (row < N) {
#pragma unroll
                for (int nf = 0; nf < 4; nf++) {
                    int col = cb + nf * 8;
                    float2 ev = *reinterpret_cast<const float2*>(
                        ent + (size_t)row * H + col);
                    float2 o = make_float2(ev.x + osum[f][nf][2 * hh],
                                           ev.y + osum[f][nf][2 * hh + 1]);
                    *reinterpret_cast<float2*>(out + (size_t)row * H + col) = o;
                }
            }
        }
}

// ---------------------------------------------------------------- out_rel = rel_emb @ rel_w
__global__ __launch_bounds__(256) void k_rel2(const float* __restrict__ rel,
                                              const float* __restrict__ rw,
                                              float* __restrict__ out, int R2) {
    __shared__ float rr[16][H];
    const int r0 = blockIdx.x * 16;
    const int tid = threadIdx.x;
#pragma unroll
    for (int q = 0; q < 16; q++) {
        int idx = q * 256 + tid;
        int ri = idx >> 8, ci = idx & 255;
        rr[ri][ci] = (r0 + ri < R2) ? rel[(size_t)(r0 + ri) * H + ci] : 0.f;
    }
    __syncthreads();
    float acc[16];
#pragma unroll
    for (int i = 0; i < 16; i++) acc[i] = 0.f;
#pragma unroll 4
    for (int k = 0; k < H; k++) {
        float wv = rw[(size_t)k * H + tid];
#pragma unroll
        for (int i = 0; i < 16; i++) acc[i] += rr[i][k] * wv;
    }
#pragma unroll
    for (int i = 0; i < 16; i++)
        if (r0 + i < R2) out[(size_t)(r0 + i) * H + tid] = acc[i];
}

// ---------------------------------------------------------------- launch
extern "C" void kernel_launch(void* const* d_in, const int* in_sizes, int n_in,
                              void* d_out, int out_size) {
    const float* ent    = (const float*)d_in[0];
    const float* rel    = (const float*)d_in[1];
    const float* w_edge = (const float*)d_in[2];
    const float* w_node = (const float*)d_in[3];
    const float* w_comp = (const float*)d_in[4];
    const float* rel_w  = (const float*)d_in[5];
    const int* src = (const int*)d_in[6];
    const int* dst = (const int*)d_in[7];
    const int* rid = (const int*)d_in[8];
    const int* nid = (const int*)d_in[9];
    const int N  = in_sizes[0] / H;
    const int R2 = in_sizes[1] / H;
    const int E  = in_sizes[6];
    float* out_ent = (float*)d_out;
    float* out_rel = out_ent + (size_t)N * H;

    static bool attr_set = false;
    if (!attr_set) {
        cudaFuncSetAttribute(k_gemm_mma, cudaFuncAttributeMaxDynamicSharedMemorySize,
                             GEMM_SMEM);
        attr_set = true;
    }

    const int nb_scan = (N + 1023) / 1024;
    k_wz<<<(3 * H * H + N + 255) / 256, 256>>>(w_edge, w_node, w_comp, N);
    k_hist<<<(E + 255) / 256, 256>>>(dst, E);
    k_scan_block<<<nb_scan, 1024>>>(N);
    k_scan_top<<<1, 32>>>(nb_scan);
    k_scan_add<<<(N + 255) / 256, 256>>>(N);
    k_permute<<<(E + 255) / 256, 256>>>(dst, E);
    k_edge<<<(N + 7) / 8, 256>>>(ent, rel, src, rid, nid, N);
    dim3 gg(2, (N + 127) / 128);
    k_gemm_mma<<<gg, 512, GEMM_SMEM>>>(ent, out_ent, N);
    if (R2 > 0) k_rel2<<<(R2 + 15) / 16, 256>>>(rel, rel_w, out_rel, R2);
}